// round 10
// baseline (speedup 1.0000x reference)
#include <cuda_runtime.h>
#include <cuda_fp16.h>
#include <math.h>

#define HEADS 16
#define GROUPS 4
#define BATCH 2
#define SEQ 2048
#define DM 2048
#define DKV 512
#define HD 128
#define KD 2048

// Scratch (allocation-free rule: __device__ globals)
__device__ __half g_q[BATCH * SEQ * DM];
__device__ __half g_k[BATCH * SEQ * DKV];
__device__ __half g_v[BATCH * SEQ * DKV];
__device__ __half g_xh[BATCH * SEQ * DM];
__device__ __half g_wqh[DM * KD];
__device__ __half g_wkh[DKV * KD];
__device__ __half g_wvh[DKV * KD];

// ---------------------------------------------------------------------------
// helpers
// ---------------------------------------------------------------------------
__device__ __forceinline__ float fexp2(float x) {
    float r;
    asm("ex2.approx.f32 %0, %1;" : "=f"(r) : "f"(x));
    return r;
}

__device__ __forceinline__ unsigned packh2(float lo, float hi) {
    __half2 h = __floats2half2_rn(lo, hi);
    return *reinterpret_cast<unsigned*>(&h);
}

__device__ __forceinline__ void mma16h(float c[4], const unsigned a[4],
                                       unsigned b0, unsigned b1) {
    asm volatile(
        "mma.sync.aligned.m16n8k16.row.col.f32.f16.f16.f32 "
        "{%0,%1,%2,%3}, {%4,%5,%6,%7}, {%8,%9}, {%0,%1,%2,%3};\n"
        : "+f"(c[0]), "+f"(c[1]), "+f"(c[2]), "+f"(c[3])
        : "r"(a[0]), "r"(a[1]), "r"(a[2]), "r"(a[3]), "r"(b0), "r"(b1));
}

__device__ __forceinline__ void ldmx4(unsigned r[4], const __half* p) {
    unsigned addr = (unsigned)__cvta_generic_to_shared(p);
    asm volatile(
        "ldmatrix.sync.aligned.m8n8.x4.shared.b16 {%0,%1,%2,%3}, [%4];"
        : "=r"(r[0]), "=r"(r[1]), "=r"(r[2]), "=r"(r[3])
        : "r"(addr));
}

__device__ __forceinline__ void ldmx4t(unsigned r[4], const __half* p) {
    unsigned addr = (unsigned)__cvta_generic_to_shared(p);
    asm volatile(
        "ldmatrix.sync.aligned.m8n8.x4.trans.shared.b16 {%0,%1,%2,%3}, [%4];"
        : "=r"(r[0]), "=r"(r[1]), "=r"(r[2]), "=r"(r[3])
        : "r"(addr));
}

__device__ __forceinline__ void cpa16(__half* dst, const __half* src) {
    unsigned d = (unsigned)__cvta_generic_to_shared(dst);
    asm volatile("cp.async.cg.shared.global [%0], [%1], 16;" :: "r"(d), "l"(src));
}
#define CP_COMMIT() asm volatile("cp.async.commit_group;" ::: "memory")
#define CP_WAIT1() asm volatile("cp.async.wait_group 1;" ::: "memory")

// ---------------------------------------------------------------------------
// fp32 -> fp16 conversion (elementwise, float4 granularity)
// ---------------------------------------------------------------------------
__global__ __launch_bounds__(256) void cvt2h(const float* __restrict__ src,
                                             __half* __restrict__ dst, int n4) {
    int i = blockIdx.x * blockDim.x + threadIdx.x;
    if (i < n4) {
        float4 v = *(const float4*)(src + i * 4);
        *(uint2*)(dst + i * 4) = make_uint2(packh2(v.x, v.y), packh2(v.z, v.w));
    }
}

// ---------------------------------------------------------------------------
// Fused QKV GEMM, fp16 inputs via cp.async 3-stage pipeline, 512 threads.
// (unchanged from round 9)
// ---------------------------------------------------------------------------
#define LDGH 40
#define GSTG_H (128 * LDGH + 256 * LDGH)
#define GEMM_SMEM_BYTES (3 * GSTG_H * 2)

__global__ __launch_bounds__(512, 1) void gemm_qkv(const __half* __restrict__ xh) {
    extern __shared__ __align__(16) char gsmRaw[];
    __half* gsm = (__half*)gsmRaw;

    const int tid = threadIdx.x;
    const int w = tid >> 5;
    const int lane = tid & 31;
    const int lg = lane >> 2;
    const int t4 = lane & 3;
    const int wm = (w & 1) * 64;
    const int wn = (w >> 1) * 32;
    const int mBase = blockIdx.y * 128;
    const int nb = blockIdx.x;

    const float qscale = 0.08838834764831845f * 1.4426950408889634f;

    const __half* W;
    __half* C;
    int cN, nl0;
    float oscale;
    if (nb < 8)       { W = g_wqh; C = g_q; cN = DM;  nl0 = nb * 256;        oscale = qscale; }
    else if (nb < 10) { W = g_wkh; C = g_k; cN = DKV; nl0 = (nb - 8) * 256;  oscale = 1.f; }
    else              { W = g_wvh; C = g_v; cN = DKV; nl0 = (nb - 10) * 256; oscale = 1.f; }

    float acc[4][4][4];
#pragma unroll
    for (int mt = 0; mt < 4; mt++)
#pragma unroll
        for (int nt = 0; nt < 4; nt++)
#pragma unroll
            for (int i = 0; i < 4; i++) acc[mt][nt][i] = 0.f;

    const int arow = tid >> 2;
    const int ac8 = (tid & 3) * 8;
    const __half* apc = xh + (size_t)(mBase + arow) * KD + ac8;
    const __half* wpc0 = W + (size_t)(nl0 + arow) * KD + ac8;
    const __half* wpc1 = W + (size_t)(nl0 + 128 + arow) * KD + ac8;

    const int lmRow = lane & 15;
    const int lmColH = (lane >> 4) * 8;
    const int ktiles = KD / 32;

#pragma unroll
    for (int t = 0; t < 2; t++) {
        __half* As = gsm + t * GSTG_H;
        __half* Bs = As + 128 * LDGH;
        cpa16(&As[arow * LDGH + ac8], apc + t * 32);
        cpa16(&Bs[arow * LDGH + ac8], wpc0 + t * 32);
        cpa16(&Bs[(128 + arow) * LDGH + ac8], wpc1 + t * 32);
        CP_COMMIT();
    }

    for (int kt = 0; kt < ktiles; kt++) {
        CP_WAIT1();
        __syncthreads();

        if (kt + 2 < ktiles) {
            __half* As = gsm + ((kt + 2) % 3) * GSTG_H;
            __half* Bs = As + 128 * LDGH;
            const int off = (kt + 2) * 32;
            cpa16(&As[arow * LDGH + ac8], apc + off);
            cpa16(&Bs[arow * LDGH + ac8], wpc0 + off);
            cpa16(&Bs[(128 + arow) * LDGH + ac8], wpc1 + off);
        }
        CP_COMMIT();

        const __half* As = gsm + (kt % 3) * GSTG_H;
        const __half* Bs = As + 128 * LDGH;
#pragma unroll
        for (int ks = 0; ks < 2; ks++) {
            const int k0 = ks * 16;
            unsigned af[4][4], bf[2][4];
#pragma unroll
            for (int mt = 0; mt < 4; mt++)
                ldmx4(af[mt], &As[(wm + mt * 16 + lmRow) * LDGH + k0 + lmColH]);
#pragma unroll
            for (int ntp = 0; ntp < 2; ntp++)
                ldmx4(bf[ntp], &Bs[(wn + ntp * 16 + lmRow) * LDGH + k0 + lmColH]);
#pragma unroll
            for (int mt = 0; mt < 4; mt++)
#pragma unroll
                for (int nt = 0; nt < 4; nt++)
                    mma16h(acc[mt][nt], af[mt], bf[nt >> 1][nt & 1],
                           bf[nt >> 1][(nt & 1) + 2]);
        }
    }

#pragma unroll
    for (int mt = 0; mt < 4; mt++)
#pragma unroll
        for (int nt = 0; nt < 4; nt++) {
            const int row = mBase + wm + mt * 16 + lg;
            const int col = nl0 + wn + nt * 8 + 2 * t4;
            *(__half2*)&C[(size_t)row * cN + col] =
                __floats2half2_rn(acc[mt][nt][0] * oscale, acc[mt][nt][1] * oscale);
            *(__half2*)&C[(size_t)(row + 8) * cN + col] =
                __floats2half2_rn(acc[mt][nt][2] * oscale, acc[mt][nt][3] * oscale);
        }
}

// ---------------------------------------------------------------------------
// fp16 flash attention: 4 warps, BQ=64, BK=64, 2-stage cp.async,
// 3 CTAs/SM. Same per-row arithmetic as round 8/9.
// ---------------------------------------------------------------------------
#define BQ 64
#define BK 64
#define LDQH 136
#define LDKH 136
#define LDVH 136
#define ASTG_H (2 * BK * LDKH)               // K+V halfs per stage = 17408
#define ATTN_SMEM_BYTES (2 * ASTG_H * 2)     // 69632

__global__ __launch_bounds__(128, 3) void attn_mma(const __half* __restrict__ q,
                                                   const __half* __restrict__ k,
                                                   const __half* __restrict__ v,
                                                   float* __restrict__ out) {
    extern __shared__ __align__(16) char smRaw[];
    __half* stg = (__half*)smRaw;          // 2 stages: [Ks|Vs] each
    __half* Qstage = (__half*)smRaw;       // overlay (pre-loop only, 17.4KB < stage0)

    const int tid = threadIdx.x;
    const int w = tid >> 5;                // 0..3
    const int lane = tid & 31;
    const int lg = lane >> 2;
    const int t4 = lane & 3;

    const int qt = gridDim.x - 1 - blockIdx.x;   // heavy tiles first
    const int h = blockIdx.y;
    const int b = blockIdx.z;
    const int grp = h / (HEADS / GROUPS);
    const int qBase = qt * BQ;
    const int wq0 = w * 16;

    const int lmRow = lane & 15;
    const int lmColH = (lane >> 4) * 8;

    // ---- stage Q (pre-scaled fp16): 2 threads per row ----
    {
        const int row = tid >> 1;
        const int hsel = tid & 1;
        const __half* qp = q + (size_t)(b * SEQ + qBase + row) * DM + h * HD +
                           hsel * 64;
        __half* qd = Qstage + row * LDQH + hsel * 64;
#pragma unroll
        for (int i = 0; i < 8; i++)
            *(uint4*)(qd + i * 8) = *(const uint4*)(qp + i * 8);
    }
    __syncthreads();

    unsigned qf[8][4];
#pragma unroll
    for (int ks = 0; ks < 8; ks++)
        ldmx4(qf[ks], &Qstage[(wq0 + lmRow) * LDQH + ks * 16 + lmColH]);
    __syncthreads();   // qf pulled before cp.async overwrites Qstage

    const int nkt = qt + 1;
    const int krow = tid >> 1;             // 0..63
    const int khalf = tid & 1;             // 64-col half
    const size_t kvcol = grp * HD + khalf * 64;

    // prologue: tiles 0,1 -> stages 0,1 (commit even if empty)
#pragma unroll
    for (int t = 0; t < 2; t++) {
        if (t < nkt) {
            __half* Ks = stg + t * ASTG_H;
            __half* Vs = Ks + BK * LDKH;
            const size_t base = (size_t)(b * SEQ + t * BK + krow) * DKV + kvcol;
            __half* kd = Ks + krow * LDKH + khalf * 64;
            __half* vd = Vs + krow * LDVH + khalf * 64;
#pragma unroll
            for (int i = 0; i < 8; i++) {
                cpa16(kd + i * 8, k + base + i * 8);
                cpa16(vd + i * 8, v + base + i * 8);
            }
        }
        CP_COMMIT();
    }

    float oacc[16][4];
#pragma unroll
    for (int nt = 0; nt < 16; nt++)
#pragma unroll
        for (int i = 0; i < 4; i++) oacc[nt][i] = 0.f;

    float m0 = -1e30f, m1 = -1e30f, l0 = 0.f, l1 = 0.f;
    const int row0g = qBase + wq0 + lg;

    for (int kt = 0; kt < nkt; kt++) {
        const int kBase = kt * BK;
        CP_WAIT1();
        __syncthreads();

        const __half* Ks = stg + (kt & 1) * ASTG_H;
        const __half* Vs = Ks + BK * LDKH;

        // ---- phase A: S = Q K^T ----
        float sacc[8][4];
#pragma unroll
        for (int nt = 0; nt < 8; nt++)
#pragma unroll
            for (int i = 0; i < 4; i++) sacc[nt][i] = 0.f;

#pragma unroll
        for (int ks = 0; ks < 8; ks++) {
            const int k0 = ks * 16;
#pragma unroll
            for (int ntp = 0; ntp < 4; ntp++) {
                unsigned bq[4];
                ldmx4(bq, &Ks[(ntp * 16 + lmRow) * LDKH + k0 + lmColH]);
                mma16h(sacc[2 * ntp], qf[ks], bq[0], bq[2]);
                mma16h(sacc[2 * ntp + 1], qf[ks], bq[1], bq[3]);
            }
        }

        // ---- causal mask (only on the diagonal tile) ----
        if (kBase + BK - 1 > qBase + wq0) {
#pragma unroll
            for (int nt = 0; nt < 8; nt++) {
                const int c0 = kBase + nt * 8 + 2 * t4;
                if (c0 > row0g) sacc[nt][0] = -1e30f;
                if (c0 + 1 > row0g) sacc[nt][1] = -1e30f;
                if (c0 > row0g + 8) sacc[nt][2] = -1e30f;
                if (c0 + 1 > row0g + 8) sacc[nt][3] = -1e30f;
            }
        }

        // ---- online softmax (base-2), registers + quad shfl ----
        float mx0 = -1e30f, mx1 = -1e30f;
#pragma unroll
        for (int nt = 0; nt < 8; nt++) {
            mx0 = fmaxf(mx0, fmaxf(sacc[nt][0], sacc[nt][1]));
            mx1 = fmaxf(mx1, fmaxf(sacc[nt][2], sacc[nt][3]));
        }
        mx0 = fmaxf(mx0, __shfl_xor_sync(0xffffffff, mx0, 1));
        mx0 = fmaxf(mx0, __shfl_xor_sync(0xffffffff, mx0, 2));
        mx1 = fmaxf(mx1, __shfl_xor_sync(0xffffffff, mx1, 1));
        mx1 = fmaxf(mx1, __shfl_xor_sync(0xffffffff, mx1, 2));

        const float mn0 = fmaxf(m0, mx0);
        const float mn1 = fmaxf(m1, mx1);
        const float sc0 = fexp2(m0 - mn0);
        const float sc1 = fexp2(m1 - mn1);

        float sum0 = 0.f, sum1 = 0.f;
#pragma unroll
        for (int nt = 0; nt < 8; nt++) {
            float p0 = fexp2(sacc[nt][0] - mn0);
            float p1 = fexp2(sacc[nt][1] - mn0);
            float p2 = fexp2(sacc[nt][2] - mn1);
            float p3 = fexp2(sacc[nt][3] - mn1);
            sacc[nt][0] = p0; sacc[nt][1] = p1;
            sacc[nt][2] = p2; sacc[nt][3] = p3;
            sum0 += p0 + p1;
            sum1 += p2 + p3;
        }
        sum0 += __shfl_xor_sync(0xffffffff, sum0, 1);
        sum0 += __shfl_xor_sync(0xffffffff, sum0, 2);
        sum1 += __shfl_xor_sync(0xffffffff, sum1, 1);
        sum1 += __shfl_xor_sync(0xffffffff, sum1, 2);

        l0 = l0 * sc0 + sum0;  m0 = mn0;
        l1 = l1 * sc1 + sum1;  m1 = mn1;

#pragma unroll
        for (int nt = 0; nt < 16; nt++) {
            oacc[nt][0] *= sc0;
            oacc[nt][1] *= sc0;
            oacc[nt][2] *= sc1;
            oacc[nt][3] *= sc1;
        }

        // ---- phase C: O += P V (P A-frag == S C-frag; V via ldmatrix.trans) ----
#pragma unroll
        for (int kt2 = 0; kt2 < 4; kt2++) {
            unsigned pf[4];
            pf[0] = packh2(sacc[2 * kt2][0], sacc[2 * kt2][1]);
            pf[1] = packh2(sacc[2 * kt2][2], sacc[2 * kt2][3]);
            pf[2] = packh2(sacc[2 * kt2 + 1][0], sacc[2 * kt2 + 1][1]);
            pf[3] = packh2(sacc[2 * kt2 + 1][2], sacc[2 * kt2 + 1][3]);
#pragma unroll
            for (int dblk = 0; dblk < 8; dblk++) {
                unsigned bv[4];
                ldmx4t(bv, &Vs[(kt2 * 16 + lmRow) * LDVH + dblk * 16 + lmColH]);
                mma16h(oacc[2 * dblk], pf, bv[0], bv[1]);
                mma16h(oacc[2 * dblk + 1], pf, bv[2], bv[3]);
            }
        }

        // ---- all warps done reading stage kt&1; refill it with tile kt+2 ----
        __syncthreads();
        if (kt + 2 < nkt) {
            __half* Kn = stg + (kt & 1) * ASTG_H;
            __half* Vn = Kn + BK * LDKH;
            const size_t base = (size_t)(b * SEQ + (kt + 2) * BK + krow) * DKV +
                                kvcol;
            __half* kd = Kn + krow * LDKH + khalf * 64;
            __half* vd = Vn + krow * LDVH + khalf * 64;
#pragma unroll
            for (int i = 0; i < 8; i++) {
                cpa16(kd + i * 8, k + base + i * 8);
                cpa16(vd + i * 8, v + base + i * 8);
            }
        }
        CP_COMMIT();
    }

    // ---- finalize + write (fp32) ----
    const float inv0 = 1.0f / l0;
    const float inv1 = 1.0f / l1;
#pragma unroll
    for (int nt = 0; nt < 16; nt++) {
        const int d = h * HD + nt * 8 + 2 * t4;
        *(float2*)&out[(size_t)(b * SEQ + row0g) * DM + d] =
            make_float2(oacc[nt][0] * inv0, oacc[nt][1] * inv0);
        *(float2*)&out[(size_t)(b * SEQ + row0g + 8) * DM + d] =
            make_float2(oacc[nt][2] * inv1, oacc[nt][3] * inv1);
    }
}

// ---------------------------------------------------------------------------
extern "C" void kernel_launch(void* const* d_in, const int* in_sizes, int n_in,
                              void* d_out, int out_size) {
    const float* x = (const float*)d_in[0];
    const float* Wq = (const float*)d_in[1];
    const float* Wk = (const float*)d_in[2];
    const float* Wv = (const float*)d_in[3];
    float* out = (float*)d_out;

    __half *pq, *pk, *pv, *pxh, *pwq, *pwk, *pwv;
    cudaGetSymbolAddress((void**)&pq, g_q);
    cudaGetSymbolAddress((void**)&pk, g_k);
    cudaGetSymbolAddress((void**)&pv, g_v);
    cudaGetSymbolAddress((void**)&pxh, g_xh);
    cudaGetSymbolAddress((void**)&pwq, g_wqh);
    cudaGetSymbolAddress((void**)&pwk, g_wkh);
    cudaGetSymbolAddress((void**)&pwv, g_wvh);

    cvt2h<<<(BATCH * SEQ * DM / 4 + 255) / 256, 256>>>(x, pxh, BATCH * SEQ * DM / 4);
    cvt2h<<<(DM * KD / 4 + 255) / 256, 256>>>(Wq, pwq, DM * KD / 4);
    cvt2h<<<(DKV * KD / 4 + 255) / 256, 256>>>(Wk, pwk, DKV * KD / 4);
    cvt2h<<<(DKV * KD / 4 + 255) / 256, 256>>>(Wv, pwv, DKV * KD / 4);

    cudaFuncSetAttribute(gemm_qkv, cudaFuncAttributeMaxDynamicSharedMemorySize,
                         GEMM_SMEM_BYTES);
    dim3 gthr(512);
    dim3 gg(12, 32);
    gemm_qkv<<<gg, gthr, GEMM_SMEM_BYTES>>>(pxh);

    cudaFuncSetAttribute(attn_mma, cudaFuncAttributeMaxDynamicSharedMemorySize,
                         ATTN_SMEM_BYTES);
    dim3 athr(128);
    dim3 ga(SEQ / BQ, HEADS, BATCH);
    attn_mma<<<ga, athr, ATTN_SMEM_BYTES>>>(pq, pk, pv, out);
}

// round 11
// speedup vs baseline: 1.0851x; 1.0851x over previous
#include <cuda_runtime.h>
#include <cuda_fp16.h>
#include <math.h>

#define HEADS 16
#define GROUPS 4
#define BATCH 2
#define SEQ 2048
#define DM 2048
#define DKV 512
#define HD 128
#define KD 2048

// Scratch (allocation-free rule: __device__ globals)
__device__ __half g_q[BATCH * SEQ * DM];
__device__ __half g_k[BATCH * SEQ * DKV];
__device__ __half g_v[BATCH * SEQ * DKV];
__device__ __half g_xh[BATCH * SEQ * DM];
__device__ __half g_wqh[DM * KD];
__device__ __half g_wkh[DKV * KD];
__device__ __half g_wvh[DKV * KD];

// ---------------------------------------------------------------------------
// helpers
// ---------------------------------------------------------------------------
__device__ __forceinline__ float fexp2(float x) {
    float r;
    asm("ex2.approx.f32 %0, %1;" : "=f"(r) : "f"(x));
    return r;
}

__device__ __forceinline__ unsigned packh2(float lo, float hi) {
    __half2 h = __floats2half2_rn(lo, hi);
    return *reinterpret_cast<unsigned*>(&h);
}

__device__ __forceinline__ void mma16h(float c[4], const unsigned a[4],
                                       unsigned b0, unsigned b1) {
    asm volatile(
        "mma.sync.aligned.m16n8k16.row.col.f32.f16.f16.f32 "
        "{%0,%1,%2,%3}, {%4,%5,%6,%7}, {%8,%9}, {%0,%1,%2,%3};\n"
        : "+f"(c[0]), "+f"(c[1]), "+f"(c[2]), "+f"(c[3])
        : "r"(a[0]), "r"(a[1]), "r"(a[2]), "r"(a[3]), "r"(b0), "r"(b1));
}

__device__ __forceinline__ void ldmx4(unsigned r[4], const __half* p) {
    unsigned addr = (unsigned)__cvta_generic_to_shared(p);
    asm volatile(
        "ldmatrix.sync.aligned.m8n8.x4.shared.b16 {%0,%1,%2,%3}, [%4];"
        : "=r"(r[0]), "=r"(r[1]), "=r"(r[2]), "=r"(r[3])
        : "r"(addr));
}

__device__ __forceinline__ void ldmx4t(unsigned r[4], const __half* p) {
    unsigned addr = (unsigned)__cvta_generic_to_shared(p);
    asm volatile(
        "ldmatrix.sync.aligned.m8n8.x4.trans.shared.b16 {%0,%1,%2,%3}, [%4];"
        : "=r"(r[0]), "=r"(r[1]), "=r"(r[2]), "=r"(r[3])
        : "r"(addr));
}

__device__ __forceinline__ void cpa16(__half* dst, const __half* src) {
    unsigned d = (unsigned)__cvta_generic_to_shared(dst);
    asm volatile("cp.async.cg.shared.global [%0], [%1], 16;" :: "r"(d), "l"(src));
}
#define CP_COMMIT() asm volatile("cp.async.commit_group;" ::: "memory")
#define CP_WAIT1() asm volatile("cp.async.wait_group 1;" ::: "memory")

// ---------------------------------------------------------------------------
// fp32 -> fp16 conversion (elementwise, float4 granularity)
// ---------------------------------------------------------------------------
__global__ __launch_bounds__(256) void cvt2h(const float* __restrict__ src,
                                             __half* __restrict__ dst, int n4) {
    int i = blockIdx.x * blockDim.x + threadIdx.x;
    if (i < n4) {
        float4 v = *(const float4*)(src + i * 4);
        *(uint2*)(dst + i * 4) = make_uint2(packh2(v.x, v.y), packh2(v.z, v.w));
    }
}

// ---------------------------------------------------------------------------
// Fused QKV GEMM, fp16, cp.async 3-stage pipeline, k-tile 64, 512 threads.
// CTA tile 128x256x64, warp tile 64x32.
// ---------------------------------------------------------------------------
#define LDGH 72
#define GSTG_H (128 * LDGH + 256 * LDGH)
#define GEMM_SMEM_BYTES (3 * GSTG_H * 2)     // 165888

__global__ __launch_bounds__(512, 1) void gemm_qkv(const __half* __restrict__ xh) {
    extern __shared__ __align__(16) char gsmRaw[];
    __half* gsm = (__half*)gsmRaw;

    const int tid = threadIdx.x;
    const int w = tid >> 5;
    const int lane = tid & 31;
    const int lg = lane >> 2;
    const int t4 = lane & 3;
    const int wm = (w & 1) * 64;
    const int wn = (w >> 1) * 32;
    const int mBase = blockIdx.y * 128;
    const int nb = blockIdx.x;

    const float qscale = 0.08838834764831845f * 1.4426950408889634f;

    const __half* W;
    __half* C;
    int cN, nl0;
    float oscale;
    if (nb < 8)       { W = g_wqh; C = g_q; cN = DM;  nl0 = nb * 256;        oscale = qscale; }
    else if (nb < 10) { W = g_wkh; C = g_k; cN = DKV; nl0 = (nb - 8) * 256;  oscale = 1.f; }
    else              { W = g_wvh; C = g_v; cN = DKV; nl0 = (nb - 10) * 256; oscale = 1.f; }

    float acc[4][4][4];
#pragma unroll
    for (int mt = 0; mt < 4; mt++)
#pragma unroll
        for (int nt = 0; nt < 4; nt++)
#pragma unroll
            for (int i = 0; i < 4; i++) acc[mt][nt][i] = 0.f;

    // cp.async mapping: row = tid>>2 (0..127), cols (tid&3)*8 and +32
    const int arow = tid >> 2;
    const int ac8 = (tid & 3) * 8;
    const __half* apc = xh + (size_t)(mBase + arow) * KD + ac8;
    const __half* wpc0 = W + (size_t)(nl0 + arow) * KD + ac8;
    const __half* wpc1 = W + (size_t)(nl0 + 128 + arow) * KD + ac8;

    const int lmRow = lane & 15;
    const int lmColH = (lane >> 4) * 8;
    const int ktiles = KD / 64;   // 32

    // prologue: tiles 0,1 -> stages 0,1
#pragma unroll
    for (int t = 0; t < 2; t++) {
        __half* As = gsm + t * GSTG_H;
        __half* Bs = As + 128 * LDGH;
        const int off = t * 64;
        cpa16(&As[arow * LDGH + ac8], apc + off);
        cpa16(&As[arow * LDGH + ac8 + 32], apc + off + 32);
        cpa16(&Bs[arow * LDGH + ac8], wpc0 + off);
        cpa16(&Bs[arow * LDGH + ac8 + 32], wpc0 + off + 32);
        cpa16(&Bs[(128 + arow) * LDGH + ac8], wpc1 + off);
        cpa16(&Bs[(128 + arow) * LDGH + ac8 + 32], wpc1 + off + 32);
        CP_COMMIT();
    }

    for (int kt = 0; kt < ktiles; kt++) {
        CP_WAIT1();
        __syncthreads();

        if (kt + 2 < ktiles) {
            __half* As = gsm + ((kt + 2) % 3) * GSTG_H;
            __half* Bs = As + 128 * LDGH;
            const int off = (kt + 2) * 64;
            cpa16(&As[arow * LDGH + ac8], apc + off);
            cpa16(&As[arow * LDGH + ac8 + 32], apc + off + 32);
            cpa16(&Bs[arow * LDGH + ac8], wpc0 + off);
            cpa16(&Bs[arow * LDGH + ac8 + 32], wpc0 + off + 32);
            cpa16(&Bs[(128 + arow) * LDGH + ac8], wpc1 + off);
            cpa16(&Bs[(128 + arow) * LDGH + ac8 + 32], wpc1 + off + 32);
        }
        CP_COMMIT();

        const __half* As = gsm + (kt % 3) * GSTG_H;
        const __half* Bs = As + 128 * LDGH;
#pragma unroll
        for (int ks = 0; ks < 4; ks++) {
            const int k0 = ks * 16;
            unsigned af[4][4], bf[2][4];
#pragma unroll
            for (int mt = 0; mt < 4; mt++)
                ldmx4(af[mt], &As[(wm + mt * 16 + lmRow) * LDGH + k0 + lmColH]);
#pragma unroll
            for (int ntp = 0; ntp < 2; ntp++)
                ldmx4(bf[ntp], &Bs[(wn + ntp * 16 + lmRow) * LDGH + k0 + lmColH]);
#pragma unroll
            for (int mt = 0; mt < 4; mt++)
#pragma unroll
                for (int nt = 0; nt < 4; nt++)
                    mma16h(acc[mt][nt], af[mt], bf[nt >> 1][nt & 1],
                           bf[nt >> 1][(nt & 1) + 2]);
        }
    }

#pragma unroll
    for (int mt = 0; mt < 4; mt++)
#pragma unroll
        for (int nt = 0; nt < 4; nt++) {
            const int row = mBase + wm + mt * 16 + lg;
            const int col = nl0 + wn + nt * 8 + 2 * t4;
            *(__half2*)&C[(size_t)row * cN + col] =
                __floats2half2_rn(acc[mt][nt][0] * oscale, acc[mt][nt][1] * oscale);
            *(__half2*)&C[(size_t)(row + 8) * cN + col] =
                __floats2half2_rn(acc[mt][nt][2] * oscale, acc[mt][nt][3] * oscale);
        }
}

// ---------------------------------------------------------------------------
// fp16 flash attention. Br=128, 8 warps, 3-stage cp.async with 128-row
// stages processed as two 64-col sub-tiles (R9 arithmetic, half the
// barrier/wait count). 1 CTA/SM.
// ---------------------------------------------------------------------------
#define BQ 128
#define BKT 128                               // k-rows per pipeline stage
#define LDQH 136
#define LDKH 136
#define LDVH 136
#define ASTG_H (2 * BKT * LDKH)               // K+V halfs per stage = 34816
#define ATTN_SMEM_BYTES (3 * ASTG_H * 2)      // 208896

__global__ __launch_bounds__(256, 1) void attn_mma(const __half* __restrict__ q,
                                                   const __half* __restrict__ k,
                                                   const __half* __restrict__ v,
                                                   float* __restrict__ out) {
    extern __shared__ __align__(16) char smRaw[];
    __half* stg = (__half*)smRaw;          // 3 stages: [Ks(128x136) | Vs(128x136)]
    __half* Qstage = (__half*)smRaw;       // overlay (pre-loop only, 34816B)

    const int tid = threadIdx.x;
    const int w = tid >> 5;
    const int lane = tid & 31;
    const int lg = lane >> 2;
    const int t4 = lane & 3;

    const int qt = gridDim.x - 1 - blockIdx.x;   // heavy tiles first
    const int h = blockIdx.y;
    const int b = blockIdx.z;
    const int grp = h / (HEADS / GROUPS);
    const int qBase = qt * BQ;
    const int wq0 = w * 16;

    const int lmRow = lane & 15;
    const int lmColH = (lane >> 4) * 8;

    // ---- stage Q (pre-scaled fp16) and pull fragments ----
    {
        const int row = tid & 127;
        const int hsel = tid >> 7;
        const __half* qp = q + (size_t)(b * SEQ + qBase + row) * DM + h * HD +
                           hsel * 64;
        __half* qd = Qstage + row * LDQH + hsel * 64;
#pragma unroll
        for (int i = 0; i < 8; i++)
            *(uint4*)(qd + i * 8) = *(const uint4*)(qp + i * 8);
    }
    __syncthreads();

    unsigned qf[8][4];
#pragma unroll
    for (int ks = 0; ks < 8; ks++)
        ldmx4(qf[ks], &Qstage[(wq0 + lmRow) * LDQH + ks * 16 + lmColH]);
    __syncthreads();   // qf pulled before cp.async overwrites Qstage

    const int nkt = (qBase + BQ) / BKT;   // = qt + 1, >= 1
    const int krow = tid >> 1;            // 0..127
    const int khalf = tid & 1;            // 64-col half
    const size_t kvcol = grp * HD + khalf * 64;

    // prologue: tiles 0,1 -> stages 0,1 (commit even if beyond nkt)
#pragma unroll
    for (int t = 0; t < 2; t++) {
        if (t < nkt) {
            __half* Ks = stg + t * ASTG_H;
            __half* Vs = Ks + BKT * LDKH;
            const size_t base = (size_t)(b * SEQ + t * BKT + krow) * DKV + kvcol;
            __half* kd = Ks + krow * LDKH + khalf * 64;
            __half* vd = Vs + krow * LDVH + khalf * 64;
#pragma unroll
            for (int i = 0; i < 8; i++) {
                cpa16(kd + i * 8, k + base + i * 8);
                cpa16(vd + i * 8, v + base + i * 8);
            }
        }
        CP_COMMIT();
    }

    float oacc[16][4];
#pragma unroll
    for (int nt = 0; nt < 16; nt++)
#pragma unroll
        for (int i = 0; i < 4; i++) oacc[nt][i] = 0.f;

    float m0 = -1e30f, m1 = -1e30f, l0 = 0.f, l1 = 0.f;
    const int lastRow = qBase + wq0 + 15;
    const int row0g = qBase + wq0 + lg;

    for (int kt = 0; kt < nkt; kt++) {
        CP_WAIT1();
        __syncthreads();

        // refill: tile kt+2 into stage (kt+2)%3 (freed at iter kt-1)
        if (kt + 2 < nkt) {
            __half* Ks = stg + ((kt + 2) % 3) * ASTG_H;
            __half* Vs = Ks + BKT * LDKH;
            const size_t base = (size_t)(b * SEQ + (kt + 2) * BKT + krow) * DKV +
                                kvcol;
            __half* kd = Ks + krow * LDKH + khalf * 64;
            __half* vd = Vs + krow * LDVH + khalf * 64;
#pragma unroll
            for (int i = 0; i < 8; i++) {
                cpa16(kd + i * 8, k + base + i * 8);
                cpa16(vd + i * 8, v + base + i * 8);
            }
        }
        CP_COMMIT();

        const __half* KsT = stg + (kt % 3) * ASTG_H;
        const __half* VsT = KsT + BKT * LDKH;

        // ---- two 64-col sub-tiles, identical arithmetic order to R9 ----
#pragma unroll
        for (int sub = 0; sub < 2; sub++) {
            const int kBase = kt * BKT + sub * 64;
            if (kBase > lastRow) continue;   // warp-uniform skip

            const __half* Ks = KsT + (sub * 64) * LDKH;
            const __half* Vs = VsT + (sub * 64) * LDVH;

            // ---- phase A: S = Q K^T ----
            float sacc[8][4];
#pragma unroll
            for (int nt = 0; nt < 8; nt++)
#pragma unroll
                for (int i = 0; i < 4; i++) sacc[nt][i] = 0.f;

#pragma unroll
            for (int ks = 0; ks < 8; ks++) {
                const int k0 = ks * 16;
#pragma unroll
                for (int ntp = 0; ntp < 4; ntp++) {
                    unsigned bq[4];
                    ldmx4(bq, &Ks[(ntp * 16 + lmRow) * LDKH + k0 + lmColH]);
                    mma16h(sacc[2 * ntp], qf[ks], bq[0], bq[2]);
                    mma16h(sacc[2 * ntp + 1], qf[ks], bq[1], bq[3]);
                }
            }

            // ---- causal mask ----
            if (kBase + 63 > qBase + wq0) {
#pragma unroll
                for (int nt = 0; nt < 8; nt++) {
                    const int c0 = kBase + nt * 8 + 2 * t4;
                    if (c0 > row0g) sacc[nt][0] = -1e30f;
                    if (c0 + 1 > row0g) sacc[nt][1] = -1e30f;
                    if (c0 > row0g + 8) sacc[nt][2] = -1e30f;
                    if (c0 + 1 > row0g + 8) sacc[nt][3] = -1e30f;
                }
            }

            // ---- online softmax (base-2), registers + quad shfl ----
            float mx0 = -1e30f, mx1 = -1e30f;
#pragma unroll
            for (int nt = 0; nt < 8; nt++) {
                mx0 = fmaxf(mx0, fmaxf(sacc[nt][0], sacc[nt][1]));
                mx1 = fmaxf(mx1, fmaxf(sacc[nt][2], sacc[nt][3]));
            }
            mx0 = fmaxf(mx0, __shfl_xor_sync(0xffffffff, mx0, 1));
            mx0 = fmaxf(mx0, __shfl_xor_sync(0xffffffff, mx0, 2));
            mx1 = fmaxf(mx1, __shfl_xor_sync(0xffffffff, mx1, 1));
            mx1 = fmaxf(mx1, __shfl_xor_sync(0xffffffff, mx1, 2));

            const float mn0 = fmaxf(m0, mx0);
            const float mn1 = fmaxf(m1, mx1);
            const float sc0 = fexp2(m0 - mn0);
            const float sc1 = fexp2(m1 - mn1);

            float sum0 = 0.f, sum1 = 0.f;
#pragma unroll
            for (int nt = 0; nt < 8; nt++) {
                float p0 = fexp2(sacc[nt][0] - mn0);
                float p1 = fexp2(sacc[nt][1] - mn0);
                float p2 = fexp2(sacc[nt][2] - mn1);
                float p3 = fexp2(sacc[nt][3] - mn1);
                sacc[nt][0] = p0; sacc[nt][1] = p1;
                sacc[nt][2] = p2; sacc[nt][3] = p3;
                sum0 += p0 + p1;
                sum1 += p2 + p3;
            }
            sum0 += __shfl_xor_sync(0xffffffff, sum0, 1);
            sum0 += __shfl_xor_sync(0xffffffff, sum0, 2);
            sum1 += __shfl_xor_sync(0xffffffff, sum1, 1);
            sum1 += __shfl_xor_sync(0xffffffff, sum1, 2);

            l0 = l0 * sc0 + sum0;  m0 = mn0;
            l1 = l1 * sc1 + sum1;  m1 = mn1;

#pragma unroll
            for (int nt = 0; nt < 16; nt++) {
                oacc[nt][0] *= sc0;
                oacc[nt][1] *= sc0;
                oacc[nt][2] *= sc1;
                oacc[nt][3] *= sc1;
            }

            // ---- phase C: O += P V ----
#pragma unroll
            for (int kt2 = 0; kt2 < 4; kt2++) {
                unsigned pf[4];
                pf[0] = packh2(sacc[2 * kt2][0], sacc[2 * kt2][1]);
                pf[1] = packh2(sacc[2 * kt2][2], sacc[2 * kt2][3]);
                pf[2] = packh2(sacc[2 * kt2 + 1][0], sacc[2 * kt2 + 1][1]);
                pf[3] = packh2(sacc[2 * kt2 + 1][2], sacc[2 * kt2 + 1][3]);
#pragma unroll
                for (int dblk = 0; dblk < 8; dblk++) {
                    unsigned bv[4];
                    ldmx4t(bv, &Vs[(kt2 * 16 + lmRow) * LDVH + dblk * 16 + lmColH]);
                    mma16h(oacc[2 * dblk], pf, bv[0], bv[1]);
                    mma16h(oacc[2 * dblk + 1], pf, bv[2], bv[3]);
                }
            }
        }
    }

    // ---- finalize + write (fp32) ----
    const float inv0 = 1.0f / l0;
    const float inv1 = 1.0f / l1;
#pragma unroll
    for (int nt = 0; nt < 16; nt++) {
        const int d = h * HD + nt * 8 + 2 * t4;
        *(float2*)&out[(size_t)(b * SEQ + row0g) * DM + d] =
            make_float2(oacc[nt][0] * inv0, oacc[nt][1] * inv0);
        *(float2*)&out[(size_t)(b * SEQ + row0g + 8) * DM + d] =
            make_float2(oacc[nt][2] * inv1, oacc[nt][3] * inv1);
    }
}

// ---------------------------------------------------------------------------
extern "C" void kernel_launch(void* const* d_in, const int* in_sizes, int n_in,
                              void* d_out, int out_size) {
    const float* x = (const float*)d_in[0];
    const float* Wq = (const float*)d_in[1];
    const float* Wk = (const float*)d_in[2];
    const float* Wv = (const float*)d_in[3];
    float* out = (float*)d_out;

    __half *pq, *pk, *pv, *pxh, *pwq, *pwk, *pwv;
    cudaGetSymbolAddress((void**)&pq, g_q);
    cudaGetSymbolAddress((void**)&pk, g_k);
    cudaGetSymbolAddress((void**)&pv, g_v);
    cudaGetSymbolAddress((void**)&pxh, g_xh);
    cudaGetSymbolAddress((void**)&pwq, g_wqh);
    cudaGetSymbolAddress((void**)&pwk, g_wkh);
    cudaGetSymbolAddress((void**)&pwv, g_wvh);

    cvt2h<<<(BATCH * SEQ * DM / 4 + 255) / 256, 256>>>(x, pxh, BATCH * SEQ * DM / 4);
    cvt2h<<<(DM * KD / 4 + 255) / 256, 256>>>(Wq, pwq, DM * KD / 4);
    cvt2h<<<(DKV * KD / 4 + 255) / 256, 256>>>(Wk, pwk, DKV * KD / 4);
    cvt2h<<<(DKV * KD / 4 + 255) / 256, 256>>>(Wv, pwv, DKV * KD / 4);

    cudaFuncSetAttribute(gemm_qkv, cudaFuncAttributeMaxDynamicSharedMemorySize,
                         GEMM_SMEM_BYTES);
    dim3 gthr(512);
    dim3 gg(12, 32);
    gemm_qkv<<<gg, gthr, GEMM_SMEM_BYTES>>>(pxh);

    cudaFuncSetAttribute(attn_mma, cudaFuncAttributeMaxDynamicSharedMemorySize,
                         ATTN_SMEM_BYTES);
    dim3 athr(256);
    dim3 ga(SEQ / BQ, HEADS, BATCH);
    attn_mma<<<ga, athr, ATTN_SMEM_BYTES>>>(pq, pk, pv, out);
}

// round 16
// speedup vs baseline: 1.1055x; 1.0187x over previous
#include <cuda_runtime.h>
#include <cuda_fp16.h>
#include <math.h>

#define HEADS 16
#define GROUPS 4
#define BATCH 2
#define SEQ 2048
#define DM 2048
#define DKV 512
#define HD 128
#define KD 2048

// Scratch (allocation-free rule: __device__ globals)
__device__ __half g_q[BATCH * SEQ * DM];
__device__ __half g_k[BATCH * SEQ * DKV];
__device__ __half g_v[BATCH * SEQ * DKV];
__device__ __half g_xh[BATCH * SEQ * DM];
__device__ __half g_wqh[DM * KD];
__device__ __half g_wkh[DKV * KD];
__device__ __half g_wvh[DKV * KD];

// ---------------------------------------------------------------------------
// helpers
// ---------------------------------------------------------------------------
__device__ __forceinline__ float fexp2(float x) {
    float r;
    asm("ex2.approx.f32 %0, %1;" : "=f"(r) : "f"(x));
    return r;
}

__device__ __forceinline__ unsigned packh2(float lo, float hi) {
    __half2 h = __floats2half2_rn(lo, hi);
    return *reinterpret_cast<unsigned*>(&h);
}

__device__ __forceinline__ void mma16h(float c[4], const unsigned a[4],
                                       unsigned b0, unsigned b1) {
    asm volatile(
        "mma.sync.aligned.m16n8k16.row.col.f32.f16.f16.f32 "
        "{%0,%1,%2,%3}, {%4,%5,%6,%7}, {%8,%9}, {%0,%1,%2,%3};\n"
        : "+f"(c[0]), "+f"(c[1]), "+f"(c[2]), "+f"(c[3])
        : "r"(a[0]), "r"(a[1]), "r"(a[2]), "r"(a[3]), "r"(b0), "r"(b1));
}

__device__ __forceinline__ void ldmx4(unsigned r[4], const __half* p) {
    unsigned addr = (unsigned)__cvta_generic_to_shared(p);
    asm volatile(
        "ldmatrix.sync.aligned.m8n8.x4.shared.b16 {%0,%1,%2,%3}, [%4];"
        : "=r"(r[0]), "=r"(r[1]), "=r"(r[2]), "=r"(r[3])
        : "r"(addr));
}

__device__ __forceinline__ void ldmx4t(unsigned r[4], const __half* p) {
    unsigned addr = (unsigned)__cvta_generic_to_shared(p);
    asm volatile(
        "ldmatrix.sync.aligned.m8n8.x4.trans.shared.b16 {%0,%1,%2,%3}, [%4];"
        : "=r"(r[0]), "=r"(r[1]), "=r"(r[2]), "=r"(r[3])
        : "r"(addr));
}

__device__ __forceinline__ void cpa16(__half* dst, const __half* src) {
    unsigned d = (unsigned)__cvta_generic_to_shared(dst);
    asm volatile("cp.async.cg.shared.global [%0], [%1], 16;" :: "r"(d), "l"(src));
}
#define CP_COMMIT() asm volatile("cp.async.commit_group;" ::: "memory")
#define CP_WAIT1() asm volatile("cp.async.wait_group 1;" ::: "memory")

// ---------------------------------------------------------------------------
// fp32 -> fp16 conversion (elementwise, float4 granularity)
// ---------------------------------------------------------------------------
__global__ __launch_bounds__(256) void cvt2h(const float* __restrict__ src,
                                             __half* __restrict__ dst, int n4) {
    int i = blockIdx.x * blockDim.x + threadIdx.x;
    if (i < n4) {
        float4 v = *(const float4*)(src + i * 4);
        *(uint2*)(dst + i * 4) = make_uint2(packh2(v.x, v.y), packh2(v.z, v.w));
    }
}

// ---------------------------------------------------------------------------
// Fused QKV GEMM, fp16 inputs via cp.async 3-stage pipeline, 512 threads.
// CTA tile 128x256x32, warp tile 64x32.  (R9 proven version)
// ---------------------------------------------------------------------------
#define LDGH 40
#define GSTG_H (128 * LDGH + 256 * LDGH)
#define GEMM_SMEM_BYTES (3 * GSTG_H * 2)

__global__ __launch_bounds__(512, 1) void gemm_qkv(const __half* __restrict__ xh) {
    extern __shared__ __align__(16) char gsmRaw[];
    __half* gsm = (__half*)gsmRaw;

    const int tid = threadIdx.x;
    const int w = tid >> 5;
    const int lane = tid & 31;
    const int lg = lane >> 2;
    const int t4 = lane & 3;
    const int wm = (w & 1) * 64;
    const int wn = (w >> 1) * 32;
    const int mBase = blockIdx.y * 128;
    const int nb = blockIdx.x;

    const float qscale = 0.08838834764831845f * 1.4426950408889634f;

    const __half* W;
    __half* C;
    int cN, nl0;
    float oscale;
    if (nb < 8)       { W = g_wqh; C = g_q; cN = DM;  nl0 = nb * 256;        oscale = qscale; }
    else if (nb < 10) { W = g_wkh; C = g_k; cN = DKV; nl0 = (nb - 8) * 256;  oscale = 1.f; }
    else              { W = g_wvh; C = g_v; cN = DKV; nl0 = (nb - 10) * 256; oscale = 1.f; }

    float acc[4][4][4];
#pragma unroll
    for (int mt = 0; mt < 4; mt++)
#pragma unroll
        for (int nt = 0; nt < 4; nt++)
#pragma unroll
            for (int i = 0; i < 4; i++) acc[mt][nt][i] = 0.f;

    const int arow = tid >> 2;
    const int ac8 = (tid & 3) * 8;
    const __half* apc = xh + (size_t)(mBase + arow) * KD + ac8;
    const __half* wpc0 = W + (size_t)(nl0 + arow) * KD + ac8;
    const __half* wpc1 = W + (size_t)(nl0 + 128 + arow) * KD + ac8;

    const int lmRow = lane & 15;
    const int lmColH = (lane >> 4) * 8;
    const int ktiles = KD / 32;

#pragma unroll
    for (int t = 0; t < 2; t++) {
        __half* As = gsm + t * GSTG_H;
        __half* Bs = As + 128 * LDGH;
        cpa16(&As[arow * LDGH + ac8], apc + t * 32);
        cpa16(&Bs[arow * LDGH + ac8], wpc0 + t * 32);
        cpa16(&Bs[(128 + arow) * LDGH + ac8], wpc1 + t * 32);
        CP_COMMIT();
    }

    for (int kt = 0; kt < ktiles; kt++) {
        CP_WAIT1();
        __syncthreads();

        if (kt + 2 < ktiles) {
            __half* As = gsm + ((kt + 2) % 3) * GSTG_H;
            __half* Bs = As + 128 * LDGH;
            const int off = (kt + 2) * 32;
            cpa16(&As[arow * LDGH + ac8], apc + off);
            cpa16(&Bs[arow * LDGH + ac8], wpc0 + off);
            cpa16(&Bs[(128 + arow) * LDGH + ac8], wpc1 + off);
        }
        CP_COMMIT();

        const __half* As = gsm + (kt % 3) * GSTG_H;
        const __half* Bs = As + 128 * LDGH;
#pragma unroll
        for (int ks = 0; ks < 2; ks++) {
            const int k0 = ks * 16;
            unsigned af[4][4], bf[2][4];
#pragma unroll
            for (int mt = 0; mt < 4; mt++)
                ldmx4(af[mt], &As[(wm + mt * 16 + lmRow) * LDGH + k0 + lmColH]);
#pragma unroll
            for (int ntp = 0; ntp < 2; ntp++)
                ldmx4(bf[ntp], &Bs[(wn + ntp * 16 + lmRow) * LDGH + k0 + lmColH]);
#pragma unroll
            for (int mt = 0; mt < 4; mt++)
#pragma unroll
                for (int nt = 0; nt < 4; nt++)
                    mma16h(acc[mt][nt], af[mt], bf[nt >> 1][nt & 1],
                           bf[nt >> 1][(nt & 1) + 2]);
        }
    }

#pragma unroll
    for (int mt = 0; mt < 4; mt++)
#pragma unroll
        for (int nt = 0; nt < 4; nt++) {
            const int row = mBase + wm + mt * 16 + lg;
            const int col = nl0 + wn + nt * 8 + 2 * t4;
            *(__half2*)&C[(size_t)row * cN + col] =
                __floats2half2_rn(acc[mt][nt][0] * oscale, acc[mt][nt][1] * oscale);
            *(__half2*)&C[(size_t)(row + 8) * cN + col] =
                __floats2half2_rn(acc[mt][nt][2] * oscale, acc[mt][nt][3] * oscale);
        }
}

// ---------------------------------------------------------------------------
// fp16 flash attention. Br=128, 8 warps, 3-stage cp.async, 128-row k-tiles
// processed with ONE joint softmax per tile (halved serial overhead).
// ---------------------------------------------------------------------------
#define BQ 128
#define BKT 128
#define LDQH 136
#define LDKH 136
#define LDVH 136
#define ASTG_H (2 * BKT * LDKH)               // 34816 halfs per stage
#define ATTN_SMEM_BYTES (3 * ASTG_H * 2)      // 208896

__global__ __launch_bounds__(256, 1) void attn_mma(const __half* __restrict__ q,
                                                   const __half* __restrict__ k,
                                                   const __half* __restrict__ v,
                                                   float* __restrict__ out) {
    extern __shared__ __align__(16) char smRaw[];
    __half* stg = (__half*)smRaw;
    __half* Qstage = (__half*)smRaw;       // overlay (pre-loop only)

    const int tid = threadIdx.x;
    const int w = tid >> 5;
    const int lane = tid & 31;
    const int lg = lane >> 2;
    const int t4 = lane & 3;

    const int qt = gridDim.x - 1 - blockIdx.x;   // heavy tiles first
    const int h = blockIdx.y;
    const int b = blockIdx.z;
    const int grp = h / (HEADS / GROUPS);
    const int qBase = qt * BQ;
    const int wq0 = w * 16;

    const int lmRow = lane & 15;
    const int lmColH = (lane >> 4) * 8;

    // ---- stage Q (pre-scaled fp16) and pull fragments ----
    {
        const int row = tid & 127;
        const int hsel = tid >> 7;
        const __half* qp = q + (size_t)(b * SEQ + qBase + row) * DM + h * HD +
                           hsel * 64;
        __half* qd = Qstage + row * LDQH + hsel * 64;
#pragma unroll
        for (int i = 0; i < 8; i++)
            *(uint4*)(qd + i * 8) = *(const uint4*)(qp + i * 8);
    }
    __syncthreads();

    unsigned qf[8][4];
#pragma unroll
    for (int ks = 0; ks < 8; ks++)
        ldmx4(qf[ks], &Qstage[(wq0 + lmRow) * LDQH + ks * 16 + lmColH]);
    __syncthreads();   // qf pulled before cp.async overwrites Qstage

    const int nkt = qt + 1;
    const int krow = tid >> 1;            // 0..127
    const int khalf = tid & 1;
    const size_t kvcol = grp * HD + khalf * 64;

    // prologue: tiles 0,1 -> stages 0,1
#pragma unroll
    for (int t = 0; t < 2; t++) {
        if (t < nkt) {
            __half* Ks = stg + t * ASTG_H;
            __half* Vs = Ks + BKT * LDKH;
            const size_t base = (size_t)(b * SEQ + t * BKT + krow) * DKV + kvcol;
            __half* kd = Ks + krow * LDKH + khalf * 64;
            __half* vd = Vs + krow * LDVH + khalf * 64;
#pragma unroll
            for (int i = 0; i < 8; i++) {
                cpa16(kd + i * 8, k + base + i * 8);
                cpa16(vd + i * 8, v + base + i * 8);
            }
        }
        CP_COMMIT();
    }

    float oacc[16][4];
#pragma unroll
    for (int nt = 0; nt < 16; nt++)
#pragma unroll
        for (int i = 0; i < 4; i++) oacc[nt][i] = 0.f;

    float m0 = -1e30f, m1 = -1e30f, l0 = 0.f, l1 = 0.f;
    const int row0g = qBase + wq0 + lg;

    for (int kt = 0; kt < nkt; kt++) {
        const int kBase = kt * BKT;
        CP_WAIT1();
        __syncthreads();

        // refill tile kt+2 into the stage freed at iter kt-1
        if (kt + 2 < nkt) {
            __half* Ks = stg + ((kt + 2) % 3) * ASTG_H;
            __half* Vs = Ks + BKT * LDKH;
            const size_t base = (size_t)(b * SEQ + (kt + 2) * BKT + krow) * DKV +
                                kvcol;
            __half* kd = Ks + krow * LDKH + khalf * 64;
            __half* vd = Vs + krow * LDVH + khalf * 64;
#pragma unroll
            for (int i = 0; i < 8; i++) {
                cpa16(kd + i * 8, k + base + i * 8);
                cpa16(vd + i * 8, v + base + i * 8);
            }
        }
        CP_COMMIT();

        const __half* Ks = stg + (kt % 3) * ASTG_H;
        const __half* Vs = Ks + BKT * LDKH;

        // ---- phase A: S = Q K^T over all 128 cols ----
        float sacc[16][4];
#pragma unroll
        for (int nt = 0; nt < 16; nt++)
#pragma unroll
            for (int i = 0; i < 4; i++) sacc[nt][i] = 0.f;

#pragma unroll
        for (int ks = 0; ks < 8; ks++) {
            const int k0 = ks * 16;
#pragma unroll
            for (int ntp = 0; ntp < 8; ntp++) {
                unsigned bq[4];
                ldmx4(bq, &Ks[(ntp * 16 + lmRow) * LDKH + k0 + lmColH]);
                mma16h(sacc[2 * ntp], qf[ks], bq[0], bq[2]);
                mma16h(sacc[2 * ntp + 1], qf[ks], bq[1], bq[3]);
            }
        }

        // ---- causal mask (only the diagonal tile needs it) ----
        if (kt == nkt - 1) {
#pragma unroll
            for (int nt = 0; nt < 16; nt++) {
                const int c0 = kBase + nt * 8 + 2 * t4;
                if (c0 > row0g) sacc[nt][0] = -1e30f;
                if (c0 + 1 > row0g) sacc[nt][1] = -1e30f;
                if (c0 > row0g + 8) sacc[nt][2] = -1e30f;
                if (c0 + 1 > row0g + 8) sacc[nt][3] = -1e30f;
            }
        }

        // ---- joint online softmax over 128 cols ----
        float mx0 = -1e30f, mx1 = -1e30f;
#pragma unroll
        for (int nt = 0; nt < 16; nt++) {
            mx0 = fmaxf(mx0, fmaxf(sacc[nt][0], sacc[nt][1]));
            mx1 = fmaxf(mx1, fmaxf(sacc[nt][2], sacc[nt][3]));
        }
        mx0 = fmaxf(mx0, __shfl_xor_sync(0xffffffff, mx0, 1));
        mx0 = fmaxf(mx0, __shfl_xor_sync(0xffffffff, mx0, 2));
        mx1 = fmaxf(mx1, __shfl_xor_sync(0xffffffff, mx1, 1));
        mx1 = fmaxf(mx1, __shfl_xor_sync(0xffffffff, mx1, 2));

        const float mn0 = fmaxf(m0, mx0);
        const float mn1 = fmaxf(m1, mx1);
        const float sc0 = fexp2(m0 - mn0);
        const float sc1 = fexp2(m1 - mn1);

        float sum0 = 0.f, sum1 = 0.f;
#pragma unroll
        for (int nt = 0; nt < 16; nt++) {
            float p0 = fexp2(sacc[nt][0] - mn0);
            float p1 = fexp2(sacc[nt][1] - mn0);
            float p2 = fexp2(sacc[nt][2] - mn1);
            float p3 = fexp2(sacc[nt][3] - mn1);
            sacc[nt][0] = p0; sacc[nt][1] = p1;
            sacc[nt][2] = p2; sacc[nt][3] = p3;
            sum0 += p0 + p1;
            sum1 += p2 + p3;
        }
        sum0 += __shfl_xor_sync(0xffffffff, sum0, 1);
        sum0 += __shfl_xor_sync(0xffffffff, sum0, 2);
        sum1 += __shfl_xor_sync(0xffffffff, sum1, 1);
        sum1 += __shfl_xor_sync(0xffffffff, sum1, 2);

        l0 = l0 * sc0 + sum0;  m0 = mn0;
        l1 = l1 * sc1 + sum1;  m1 = mn1;

#pragma unroll
        for (int nt = 0; nt < 16; nt++) {
            oacc[nt][0] *= sc0;
            oacc[nt][1] *= sc0;
            oacc[nt][2] *= sc1;
            oacc[nt][3] *= sc1;
        }

        // ---- phase C: O += P V over 128 k-rows ----
#pragma unroll
        for (int kt2 = 0; kt2 < 8; kt2++) {
            unsigned pf[4];
            pf[0] = packh2(sacc[2 * kt2][0], sacc[2 * kt2][1]);
            pf[1] = packh2(sacc[2 * kt2][2], sacc[2 * kt2][3]);
            pf[2] = packh2(sacc[2 * kt2 + 1][0], sacc[2 * kt2 + 1][1]);
            pf[3] = packh2(sacc[2 * kt2 + 1][2], sacc[2 * kt2 + 1][3]);
#pragma unroll
            for (int dblk = 0; dblk < 8; dblk++) {
                unsigned bv[4];
                ldmx4t(bv, &Vs[(kt2 * 16 + lmRow) * LDVH + dblk * 16 + lmColH]);
                mma16h(oacc[2 * dblk], pf, bv[0], bv[1]);
                mma16h(oacc[2 * dblk + 1], pf, bv[2], bv[3]);
            }
        }
    }

    // ---- finalize + write (fp32) ----
    const float inv0 = 1.0f / l0;
    const float inv1 = 1.0f / l1;
#pragma unroll
    for (int nt = 0; nt < 16; nt++) {
        const int d = h * HD + nt * 8 + 2 * t4;
        *(float2*)&out[(size_t)(b * SEQ + row0g) * DM + d] =
            make_float2(oacc[nt][0] * inv0, oacc[nt][1] * inv0);
        *(float2*)&out[(size_t)(b * SEQ + row0g + 8) * DM + d] =
            make_float2(oacc[nt][2] * inv1, oacc[nt][3] * inv1);
    }
}

// ---------------------------------------------------------------------------
extern "C" void kernel_launch(void* const* d_in, const int* in_sizes, int n_in,
                              void* d_out, int out_size) {
    const float* x = (const float*)d_in[0];
    const float* Wq = (const float*)d_in[1];
    const float* Wk = (const float*)d_in[2];
    const float* Wv = (const float*)d_in[3];
    float* out = (float*)d_out;

    __half *pq, *pk, *pv, *pxh, *pwq, *pwk, *pwv;
    cudaGetSymbolAddress((void**)&pq, g_q);
    cudaGetSymbolAddress((void**)&pk, g_k);
    cudaGetSymbolAddress((void**)&pv, g_v);
    cudaGetSymbolAddress((void**)&pxh, g_xh);
    cudaGetSymbolAddress((void**)&pwq, g_wqh);
    cudaGetSymbolAddress((void**)&pwk, g_wkh);
    cudaGetSymbolAddress((void**)&pwv, g_wvh);

    cvt2h<<<(BATCH * SEQ * DM / 4 + 255) / 256, 256>>>(x, pxh, BATCH * SEQ * DM / 4);
    cvt2h<<<(DM * KD / 4 + 255) / 256, 256>>>(Wq, pwq, DM * KD / 4);
    cvt2h<<<(DKV * KD / 4 + 255) / 256, 256>>>(Wk, pwk, DKV * KD / 4);
    cvt2h<<<(DKV * KD / 4 + 255) / 256, 256>>>(Wv, pwv, DKV * KD / 4);

    cudaFuncSetAttribute(gemm_qkv, cudaFuncAttributeMaxDynamicSharedMemorySize,
                         GEMM_SMEM_BYTES);
    dim3 gthr(512);
    dim3 gg(12, 32);
    gemm_qkv<<<gg, gthr, GEMM_SMEM_BYTES>>>(pxh);

    cudaFuncSetAttribute(attn_mma, cudaFuncAttributeMaxDynamicSharedMemorySize,
                         ATTN_SMEM_BYTES);
    dim3 athr(256);
    dim3 ga(SEQ / BQ, HEADS, BATCH);
    attn_mma<<<ga, athr, ATTN_SMEM_BYTES>>>(pq, pk, pv, out);
}